// round 15
// baseline (speedup 1.0000x reference)
#include <cuda_runtime.h>
#include <cuda_bf16.h>
#include <cstdint>

// Problem constants (fixed by the dataset)
#define D_   64
#define H_   64
#define EF_  16
#define PC   192    // g_P row: [src-proj(+b_e1) | dst-proj | node-proj(+b_n1)]
#define TEE  128    // edges per tile (edge kernel)
#define NMAX 50000

__device__ float g_hneigh[(size_t)NMAX * H_];
__device__ float g_P[(size_t)NMAX * PC];

typedef unsigned int u32;

__device__ __forceinline__ float silu_f(float x) {
    return __fdividef(x, 1.0f + __expf(-x));
}
__device__ __forceinline__ float silu_fast(float x) {
    float t, hx = 0.5f * x;
    asm("tanh.approx.f32 %0, %1;" : "=f"(t) : "f"(hx));
    return fmaf(hx, t, hx);
}
__device__ __forceinline__ u32 smem_u32(const void* p) {
    u32 a;
    asm("{ .reg .u64 t; cvta.to.shared.u64 t, %1; cvt.u32.u64 %0, t; }"
        : "=r"(a) : "l"(p));
    return a;
}

__global__ void zero_hneigh(int n4) {
    float4 z = make_float4(0.f, 0.f, 0.f, 0.f);
    for (int i = blockIdx.x * blockDim.x + threadIdx.x; i < n4;
         i += gridDim.x * blockDim.x)
        reinterpret_cast<float4*>(g_hneigh)[i] = z;
}

extern __shared__ float smemf[];
extern __shared__ char smemc[];

// ---- mma helpers ----
__device__ __forceinline__ void ldsm_x4(u32& r0, u32& r1, u32& r2, u32& r3, u32 a) {
    asm volatile("ldmatrix.sync.aligned.m8n8.x4.shared.b16 {%0,%1,%2,%3}, [%4];"
                 : "=r"(r0), "=r"(r1), "=r"(r2), "=r"(r3) : "r"(a));
}
__device__ __forceinline__ void ldsm_x2(u32& r0, u32& r1, u32 a) {
    asm volatile("ldmatrix.sync.aligned.m8n8.x2.shared.b16 {%0,%1}, [%2];"
                 : "=r"(r0), "=r"(r1) : "r"(a));
}
__device__ __forceinline__ void mma16816(float* d, const u32* a, const u32* b) {
    asm volatile(
        "mma.sync.aligned.m16n8k16.row.col.f32.bf16.bf16.f32 "
        "{%0,%1,%2,%3}, {%4,%5,%6,%7}, {%8,%9}, {%0,%1,%2,%3};"
        : "+f"(d[0]), "+f"(d[1]), "+f"(d[2]), "+f"(d[3])
        : "r"(a[0]), "r"(a[1]), "r"(a[2]), "r"(a[3]), "r"(b[0]), "r"(b[1]));
}
__device__ __forceinline__ void bf16_split(float x, __nv_bfloat16& h, __nv_bfloat16& l) {
    h = __float2bfloat16(x);
    l = __float2bfloat16(x - __bfloat162float(h));
}

#define MSTRIDE 144        // bytes per row of [*][64] bf16 tiles

// ---------------------------------------------------------------------------
// Precompute: g_P[n] = [ nf@We1_src + b_e1 | nf@We1_dst | nf@Wn1_top + b_n1 ]
// (standalone again — R14 proved folding the zero into this kernel costs 30us)
// ---------------------------------------------------------------------------
__global__ __launch_bounds__(256, 2) void pre_kernel(
    const float* __restrict__ node_feat,
    const float* __restrict__ W_e1, const float* __restrict__ b_e1,
    const float* __restrict__ W_n1, const float* __restrict__ b_n1, int N)
{
    float* Wp   = smemf;             // [64][192]
    float* Zs   = Wp + 64 * PC;      // [64][68]
    float* bsrc = Zs + 64 * 68;      // 64
    float* bn   = bsrc + 64;         // 64

    const int tid = threadIdx.x;
    const int tx  = tid & 31;
    const int ty  = tid >> 5;

    for (int i = tid; i < 64 * PC; i += 256) {
        int k = i / PC, c = i - k * PC;
        float v;
        if (c < 64)       v = W_e1[k * H_ + c];
        else if (c < 128) v = W_e1[(64 + k) * H_ + (c - 64)];
        else              v = W_n1[k * H_ + (c - 128)];
        Wp[i] = v;
    }
    if (tid < 64) { bsrc[tid] = b_e1[tid]; bn[tid] = b_n1[tid]; }

    const int ntiles = (N + 63) / 64;
    for (int tile = blockIdx.x; tile < ntiles; tile += gridDim.x) {
        const int n0 = tile * 64;
        __syncthreads();
        #pragma unroll
        for (int it = 0; it < 16; it++) {
            int idx = it * 256 + tid;
            int r = idx >> 6, k = idx & 63;
            int n = n0 + r;
            Zs[r * 68 + k] = (n < N) ? node_feat[n * D_ + k] : 0.f;
        }
        __syncthreads();

        float acc[8][4], accB[8][2];
        #pragma unroll
        for (int i = 0; i < 8; i++) {
            acc[i][0] = acc[i][1] = acc[i][2] = acc[i][3] = 0.f;
            accB[i][0] = accB[i][1] = 0.f;
        }
        const float* zb = &Zs[(ty * 8) * 68];
        #pragma unroll 4
        for (int k = 0; k < 64; k++) {
            const float4 w = *reinterpret_cast<const float4*>(&Wp[k * PC + tx * 4]);
            const float2 wb = *reinterpret_cast<const float2*>(&Wp[k * PC + 128 + tx * 2]);
            #pragma unroll
            for (int i = 0; i < 8; i++) {
                float z = zb[i * 68 + k];
                acc[i][0] += z * w.x; acc[i][1] += z * w.y;
                acc[i][2] += z * w.z; acc[i][3] += z * w.w;
                accB[i][0] += z * wb.x; accB[i][1] += z * wb.y;
            }
        }
        #pragma unroll
        for (int i = 0; i < 8; i++) {
            int n = n0 + ty * 8 + i;
            if (n < N) {
                float4 v = make_float4(acc[i][0], acc[i][1], acc[i][2], acc[i][3]);
                if (tx < 16) {
                    v.x += bsrc[tx * 4 + 0]; v.y += bsrc[tx * 4 + 1];
                    v.z += bsrc[tx * 4 + 2]; v.w += bsrc[tx * 4 + 3];
                }
                *reinterpret_cast<float4*>(&g_P[(size_t)n * PC + tx * 4]) = v;
                float2 vb = make_float2(accB[i][0] + bn[tx * 2],
                                        accB[i][1] + bn[tx * 2 + 1]);
                *reinterpret_cast<float2*>(&g_P[(size_t)n * PC + 128 + tx * 2]) = vb;
            }
        }
    }
}

// ---------------------------------------------------------------------------
// Edge kernel, pipelined, 2 syncs/tile, fragment-direct scatter (R14 edge).
// ---------------------------------------------------------------------------
#define EO_WR   0          // 64 f
#define EO_B2   256        // 64 f
#define EO_WA   512        // 16*64 f -> 4608
#define EO_RAD  4608       // 2 x 128 f -> 5632
#define EO_SRC  5632       // 2 x 128 i -> 6656
#define EO_DST  6656       // 2 x 128 i -> 7680
#define EO_AS   7680       // 2 x 128*17 f -> 25088
#define EO_W2HI 25088      // 64 x MSTRIDE -> 34304
#define EO_W2LO 34304      // -> 43520
#define EO_MHI  43520      // 128 x MSTRIDE -> 61952
#define EO_MLO  61952      // -> 80384
#define EO_TOT  80384

__global__ __launch_bounds__(256, 2) void edge_kernel(
    const float* __restrict__ coord, const float* __restrict__ edge_feat,
    const int* __restrict__ src, const int* __restrict__ dst,
    const float* __restrict__ W_e1, const float* __restrict__ W_e2,
    const float* __restrict__ b_e2, int E)
{
    char* smem = smemc;
    const u32 sb = smem_u32(smem);
    float* wrs = (float*)(smem + EO_WR);
    float* b2s = (float*)(smem + EO_B2);
    float* Was = (float*)(smem + EO_WA);

    const int tid = threadIdx.x;
    const int wid = tid >> 5;
    const int lid = tid & 31;
    const int tx  = tid & 15;
    const int ty  = tid >> 4;

    for (int i = tid; i < EF_ * H_; i += 256) Was[i] = W_e1[129 * H_ + i];
    if (tid < H_) { wrs[tid] = W_e1[128 * H_ + tid]; b2s[tid] = b_e2[tid]; }
    for (int i = tid; i < H_ * H_; i += 256) {
        int k = i >> 6, n = i & 63;
        __nv_bfloat16 hi, lo; bf16_split(W_e2[i], hi, lo);
        *(__nv_bfloat16*)(smem + EO_W2HI + n * MSTRIDE + k * 2) = hi;
        *(__nv_bfloat16*)(smem + EO_W2LO + n * MSTRIDE + k * 2) = lo;
    }

    const int ntiles = (E + TEE - 1) / TEE;
    int tile = blockIdx.x;
    if (tile >= ntiles) return;

#define PHASE_A(tt, bb)                                                        \
    {                                                                          \
        const int e0n = (tt) * TEE;                                            \
        float* radb = (float*)(smem + EO_RAD + (bb) * 512);                    \
        int*   srcb = (int*)(smem + EO_SRC + (bb) * 512);                      \
        int*   dstb = (int*)(smem + EO_DST + (bb) * 512);                      \
        float* Asb  = (float*)(smem + EO_AS + (bb) * 8704);                    \
        if (tid < TEE) {                                                       \
            int e = e0n + tid;                                                 \
            int s = 0, d = 0;                                                  \
            float radial = 0.f;                                                \
            if (e < E) {                                                       \
                s = src[e]; d = dst[e];                                        \
                float dx = coord[3 * s + 0] - coord[3 * d + 0];                \
                float dy = coord[3 * s + 1] - coord[3 * d + 1];                \
                float dz = coord[3 * s + 2] - coord[3 * d + 2];                \
                radial = dx * dx + dy * dy + dz * dz;                          \
            }                                                                  \
            srcb[tid] = s; dstb[tid] = d; radb[tid] = radial;                  \
        }                                                                      \
        _Pragma("unroll")                                                      \
        for (int it = 0; it < 8; it++) {                                       \
            int idx = it * 256 + tid;                                          \
            int r = idx >> 4, j = idx & 15;                                    \
            int e = e0n + r;                                                   \
            Asb[r * 17 + j] = (e < E) ? edge_feat[(size_t)e * EF_ + j] : 0.f;  \
        }                                                                      \
    }

#define GATHER(bb, ps)                                                         \
    {                                                                          \
        int* srcb = (int*)(smem + EO_SRC + (bb) * 512);                        \
        int* dstb = (int*)(smem + EO_DST + (bb) * 512);                        \
        _Pragma("unroll")                                                      \
        for (int i = 0; i < 8; i++) {                                          \
            int r = ty * 8 + i;                                                \
            float4 a = *reinterpret_cast<const float4*>(                       \
                           &g_P[(size_t)srcb[r] * PC + tx * 4]);               \
            float4 bq = *reinterpret_cast<const float4*>(                      \
                           &g_P[(size_t)dstb[r] * PC + 64 + tx * 4]);          \
            ps[i] = make_float4(a.x + bq.x, a.y + bq.y, a.z + bq.z, a.w + bq.w);\
        }                                                                      \
    }

    int b = 0;
    float4 psum[8];
    PHASE_A(tile, 0);
    __syncthreads();
    GATHER(0, psum);

    for (; tile < ntiles; tile += gridDim.x) {
        const int e0 = tile * TEE;
        const int tnext = tile + gridDim.x;
        float* radb = (float*)(smem + EO_RAD + b * 512);
        int*   dstb = (int*)(smem + EO_DST + b * 512);
        float* Asb  = (float*)(smem + EO_AS + b * 8704);

        // Stage 1: FFMA over K=16 edge features + radial, fold psum, silu, split
        const float4 wr = *reinterpret_cast<const float4*>(&wrs[tx * 4]);
        #pragma unroll
        for (int g = 0; g < 2; g++) {
            const int rbase = ty * 8 + g * 4;
            float acc[4][4];
            #pragma unroll
            for (int i = 0; i < 4; i++) {
                float rr = radb[rbase + i];
                acc[i][0] = rr * wr.x; acc[i][1] = rr * wr.y;
                acc[i][2] = rr * wr.z; acc[i][3] = rr * wr.w;
            }
            #pragma unroll
            for (int k = 0; k < EF_; k++) {
                const float4 w = *reinterpret_cast<const float4*>(&Was[k * H_ + tx * 4]);
                #pragma unroll
                for (int i = 0; i < 4; i++) {
                    float a = Asb[(rbase + i) * 17 + k];
                    acc[i][0] += a * w.x; acc[i][1] += a * w.y;
                    acc[i][2] += a * w.z; acc[i][3] += a * w.w;
                }
            }
            #pragma unroll
            for (int i = 0; i < 4; i++) {
                int r = rbase + i;
                const float4 p = psum[g * 4 + i];
                float m0 = silu_fast(acc[i][0] + p.x);
                float m1 = silu_fast(acc[i][1] + p.y);
                float m2 = silu_fast(acc[i][2] + p.z);
                float m3 = silu_fast(acc[i][3] + p.w);
                __nv_bfloat16 h0, h1, h2, h3, l0, l1, l2, l3;
                bf16_split(m0, h0, l0); bf16_split(m1, h1, l1);
                bf16_split(m2, h2, l2); bf16_split(m3, h3, l3);
                __nv_bfloat162 H01; H01.x = h0; H01.y = h1;
                __nv_bfloat162 H23; H23.x = h2; H23.y = h3;
                __nv_bfloat162 L01; L01.x = l0; L01.y = l1;
                __nv_bfloat162 L23; L23.x = l2; L23.y = l3;
                *(uint2*)(smem + EO_MHI + r * MSTRIDE + tx * 8) =
                    make_uint2(*(u32*)&H01, *(u32*)&H23);
                *(uint2*)(smem + EO_MLO + r * MSTRIDE + tx * 8) =
                    make_uint2(*(u32*)&L01, *(u32*)&L23);
            }
        }

        // Prefetch next tile's Phase A (global loads overlap with MMA2)
        if (tnext < ntiles) PHASE_A(tnext, b ^ 1);
        __syncthreads();   // M writes + PhaseA(b^1) stores visible

        // Stage 2: D = Mhi@W2hi^T + Mhi@W2lo^T + Mlo@W2hi^T
        float acc[8][4];
        {
            const int m0 = wid * 16;
            #pragma unroll
            for (int nt = 0; nt < 8; nt++)
                acc[nt][0] = acc[nt][1] = acc[nt][2] = acc[nt][3] = 0.f;

            const u32 aoff = (u32)((m0 + (lid & 15)) * MSTRIDE + (lid >> 4) * 16);
            const u32 boffR = (u32)((lid & 7) * MSTRIDE + ((lid >> 3) & 1) * 16);
            #pragma unroll
            for (int j = 0; j < 4; j++) {
                u32 ah[4], al[4];
                ldsm_x4(ah[0], ah[1], ah[2], ah[3], sb + EO_MHI + aoff + j * 32);
                ldsm_x4(al[0], al[1], al[2], al[3], sb + EO_MLO + aoff + j * 32);
                #pragma unroll
                for (int nt = 0; nt < 8; nt++) {
                    u32 bh[2], bl[2];
                    u32 boff = (u32)(nt * 8 * MSTRIDE) + boffR + j * 32;
                    ldsm_x2(bh[0], bh[1], sb + EO_W2HI + boff);
                    ldsm_x2(bl[0], bl[1], sb + EO_W2LO + boff);
                    mma16816(acc[nt], ah, bh);
                    mma16816(acc[nt], ah, bl);
                    mma16816(acc[nt], al, bh);
                }
            }
        }

        // Prefetch next tile's gathers (latency covered by epilogue/scatter)
        if (tnext < ntiles) GATHER(b ^ 1, psum);

        // Epilogue: bias + silu, scatter DIRECTLY from fragments (v2 REDG)
        {
            const int rA = wid * 16 + (lid >> 2);
            const int rB = rA + 8;
            const int c0base = (lid & 3) * 2;
            const bool okA = (e0 + rA) < E;
            const bool okB = (e0 + rB) < E;
            const int dA = okA ? dstb[rA] : 0;
            const int dB = okB ? dstb[rB] : 0;
            #pragma unroll
            for (int nt = 0; nt < 8; nt++) {
                const int c = nt * 8 + c0base;
                const float bb0 = b2s[c], bb1 = b2s[c + 1];
                if (okA) {
                    float v0 = silu_fast(acc[nt][0] + bb0);
                    float v1 = silu_fast(acc[nt][1] + bb1);
                    asm volatile("red.global.add.v2.f32 [%0], {%1,%2};"
                                 :: "l"(&g_hneigh[(size_t)dA * H_ + c]),
                                    "f"(v0), "f"(v1) : "memory");
                }
                if (okB) {
                    float v2 = silu_fast(acc[nt][2] + bb0);
                    float v3 = silu_fast(acc[nt][3] + bb1);
                    asm volatile("red.global.add.v2.f32 [%0], {%1,%2};"
                                 :: "l"(&g_hneigh[(size_t)dB * H_ + c]),
                                    "f"(v2), "f"(v3) : "memory");
                }
            }
        }
        __syncthreads();   // MMA2's M reads done before next tile's M writes
        b ^= 1;
    }
#undef PHASE_A
#undef GATHER
}

// ---------------------------------------------------------------------------
// Node kernel, tensorized (R8 winner, unchanged)
// ---------------------------------------------------------------------------
#define NO_W1HI 0
#define NO_W1LO 9216
#define NO_W2HI 18432
#define NO_W2LO 27648
#define NO_B2   36864
#define NO_ZHI  37120
#define NO_ZLO  55552
#define NO_TOT  73984

__global__ __launch_bounds__(256, 2) void node_kernel(
    const float* __restrict__ W_n1, const float* __restrict__ W_n2,
    const float* __restrict__ b_n2, float* __restrict__ out, int N)
{
    char* smem = smemc;
    const u32 sb = smem_u32(smem);
    float* b2s = (float*)(smem + NO_B2);

    const int tid = threadIdx.x;
    const int wid = tid >> 5;
    const int lid = tid & 31;

    for (int i = tid; i < 64 * 64; i += 256) {
        int c = i >> 6, k = i & 63;
        __nv_bfloat16 h, l;
        bf16_split(W_n1[(64 + k) * 64 + c], h, l);
        *(__nv_bfloat16*)(smem + NO_W1HI + c * MSTRIDE + k * 2) = h;
        *(__nv_bfloat16*)(smem + NO_W1LO + c * MSTRIDE + k * 2) = l;
        bf16_split(W_n2[k * 64 + c], h, l);
        *(__nv_bfloat16*)(smem + NO_W2HI + c * MSTRIDE + k * 2) = h;
        *(__nv_bfloat16*)(smem + NO_W2LO + c * MSTRIDE + k * 2) = l;
    }
    if (tid < 64) b2s[tid] = b_n2[tid];

    const int m0  = wid * 16;
    const int rA  = m0 + (lid >> 2);
    const int rB  = rA + 8;
    const int cfr = (lid & 3) * 2;
    const u32 aoff  = (u32)((m0 + (lid & 15)) * MSTRIDE + (lid >> 4) * 16);
    const u32 boffR = (u32)((lid & 7) * MSTRIDE + ((lid >> 3) & 1) * 16);

    const int ntiles = (N + 127) / 128;
    for (int tile = blockIdx.x; tile < ntiles; tile += gridDim.x) {
        const int n0 = tile * 128;
        __syncthreads();

        #pragma unroll
        for (int it = 0; it < 8; it++) {
            int idx = it * 256 + tid;
            int r = idx >> 4, k4 = (idx & 15) * 4;
            int n = n0 + r;
            float4 v = (n < N)
                ? *reinterpret_cast<const float4*>(&g_hneigh[(size_t)n * H_ + k4])
                : make_float4(0.f, 0.f, 0.f, 0.f);
            __nv_bfloat16 h0, h1, h2, h3, l0, l1, l2, l3;
            bf16_split(v.x, h0, l0); bf16_split(v.y, h1, l1);
            bf16_split(v.z, h2, l2); bf16_split(v.w, h3, l3);
            __nv_bfloat162 H01; H01.x = h0; H01.y = h1;
            __nv_bfloat162 H23; H23.x = h2; H23.y = h3;
            __nv_bfloat162 L01; L01.x = l0; L01.y = l1;
            __nv_bfloat162 L23; L23.x = l2; L23.y = l3;
            *(uint2*)(smem + NO_ZHI + r * MSTRIDE + k4 * 2) =
                make_uint2(*(u32*)&H01, *(u32*)&H23);
            *(uint2*)(smem + NO_ZLO + r * MSTRIDE + k4 * 2) =
                make_uint2(*(u32*)&L01, *(u32*)&L23);
        }
        __syncthreads();

        float acc[8][4];
        {
            const int nA = n0 + rA, nB = n0 + rB;
            #pragma unroll
            for (int nt = 0; nt < 8; nt++) {
                int c = nt * 8 + cfr;
                float2 pA = (nA < N)
                    ? *reinterpret_cast<const float2*>(&g_P[(size_t)nA * PC + 128 + c])
                    : make_float2(0.f, 0.f);
                float2 pB = (nB < N)
                    ? *reinterpret_cast<const float2*>(&g_P[(size_t)nB * PC + 128 + c])
                    : make_float2(0.f, 0.f);
                acc[nt][0] = pA.x; acc[nt][1] = pA.y;
                acc[nt][2] = pB.x; acc[nt][3] = pB.y;
            }
            #pragma unroll
            for (int j = 0; j < 4; j++) {
                u32 ah[4], al[4];
                ldsm_x4(ah[0], ah[1], ah[2], ah[3], sb + NO_ZHI + aoff + j * 32);
                ldsm_x4(al[0], al[1], al[2], al[3], sb + NO_ZLO + aoff + j * 32);
                #pragma unroll
                for (int nt = 0; nt < 8; nt++) {
                    u32 bh[2], bl[2];
                    u32 boff = (u32)(nt * 8 * MSTRIDE) + boffR + j * 32;
                    ldsm_x2(bh[0], bh[1], sb + NO_W1HI + boff);
                    ldsm_x2(bl[0], bl[1], sb + NO_W1LO + boff);
                    mma16816(acc[nt], ah, bh);
                    mma16816(acc[nt], ah, bl);
                    mma16816(acc[nt], al, bh);
                }
            }
        }
        __syncthreads();

        #pragma unroll
        for (int nt = 0; nt < 8; nt++) {
            int c = nt * 8 + cfr;
            float v0 = silu_f(acc[nt][0]);
            float v1 = silu_f(acc[nt][1]);
            float v2 = silu_f(acc[nt][2]);
            float v3 = silu_f(acc[nt][3]);
            __nv_bfloat16 h0, h1, h2, h3, l0, l1, l2, l3;
            bf16_split(v0, h0, l0); bf16_split(v1, h1, l1);
            bf16_split(v2, h2, l2); bf16_split(v3, h3, l3);
            __nv_bfloat162 HA; HA.x = h0; HA.y = h1;
            __nv_bfloat162 HB; HB.x = h2; HB.y = h3;
            __nv_bfloat162 LA; LA.x = l0; LA.y = l1;
            __nv_bfloat162 LB; LB.x = l2; LB.y = l3;
            *(u32*)(smem + NO_ZHI + rA * MSTRIDE + c * 2) = *(u32*)&HA;
            *(u32*)(smem + NO_ZHI + rB * MSTRIDE + c * 2) = *(u32*)&HB;
            *(u32*)(smem + NO_ZLO + rA * MSTRIDE + c * 2) = *(u32*)&LA;
            *(u32*)(smem + NO_ZLO + rB * MSTRIDE + c * 2) = *(u32*)&LB;
        }
        __syncthreads();

        float acc2[8][4];
        {
            #pragma unroll
            for (int nt = 0; nt < 8; nt++) {
                int c = nt * 8 + cfr;
                float b0 = b2s[c], b1 = b2s[c + 1];
                acc2[nt][0] = b0; acc2[nt][1] = b1;
                acc2[nt][2] = b0; acc2[nt][3] = b1;
            }
            #pragma unroll
            for (int j = 0; j < 4; j++) {
                u32 ah[4], al[4];
                ldsm_x4(ah[0], ah[1], ah[2], ah[3], sb + NO_ZHI + aoff + j * 32);
                ldsm_x4(al[0], al[1], al[2], al[3], sb + NO_ZLO + aoff + j * 32);
                #pragma unroll
                for (int nt = 0; nt < 8; nt++) {
                    u32 bh[2], bl[2];
                    u32 boff = (u32)(nt * 8 * MSTRIDE) + boffR + j * 32;
                    ldsm_x2(bh[0], bh[1], sb + NO_W2HI + boff);
                    ldsm_x2(bl[0], bl[1], sb + NO_W2LO + boff);
                    mma16816(acc2[nt], ah, bh);
                    mma16816(acc2[nt], ah, bl);
                    mma16816(acc2[nt], al, bh);
                }
            }
        }

        {
            const int nA = n0 + rA, nB = n0 + rB;
            #pragma unroll
            for (int nt = 0; nt < 8; nt++) {
                int c = nt * 8 + cfr;
                if (nA < N)
                    *reinterpret_cast<float2*>(&out[(size_t)nA * D_ + c]) =
                        make_float2(acc2[nt][0], acc2[nt][1]);
                if (nB < N)
                    *reinterpret_cast<float2*>(&out[(size_t)nB * D_ + c]) =
                        make_float2(acc2[nt][2], acc2[nt][3]);
            }
        }
    }
}

extern "C" void kernel_launch(void* const* d_in, const int* in_sizes, int n_in,
                              void* d_out, int out_size)
{
    const float* node_feat = (const float*)d_in[0];
    const float* coord     = (const float*)d_in[1];
    const float* edge_feat = (const float*)d_in[2];
    const int*   src       = (const int*)d_in[3];
    const int*   dst       = (const int*)d_in[4];
    const float* W_e1      = (const float*)d_in[5];
    const float* b_e1      = (const float*)d_in[6];
    const float* W_e2      = (const float*)d_in[7];
    const float* b_e2      = (const float*)d_in[8];
    const float* W_n1      = (const float*)d_in[9];
    const float* b_n1      = (const float*)d_in[10];
    const float* W_n2      = (const float*)d_in[11];
    const float* b_n2      = (const float*)d_in[12];
    float* out = (float*)d_out;

    const int N = in_sizes[0] / D_;
    const int E = in_sizes[3];

    const size_t smemP = (size_t)(64 * PC + 64 * 68 + 128) * 4;
    const size_t smemE = EO_TOT;
    const size_t smemN = NO_TOT;

    cudaFuncSetAttribute(pre_kernel,
                         cudaFuncAttributeMaxDynamicSharedMemorySize, (int)smemP);
    cudaFuncSetAttribute(edge_kernel,
                         cudaFuncAttributeMaxDynamicSharedMemorySize, (int)smemE);
    cudaFuncSetAttribute(node_kernel,
                         cudaFuncAttributeMaxDynamicSharedMemorySize, (int)smemN);

    zero_hneigh<<<512, 256>>>(N * H_ / 4);
    pre_kernel<<<296, 256, smemP>>>(node_feat, W_e1, b_e1, W_n1, b_n1, N);
    edge_kernel<<<296, 256, smemE>>>(coord, edge_feat, src, dst,
                                     W_e1, W_e2, b_e2, E);
    node_kernel<<<296, 256, smemN>>>(W_n1, W_n2, b_n2, out, N);
}

// round 16
// speedup vs baseline: 1.1487x; 1.1487x over previous
#include <cuda_runtime.h>
#include <cuda_bf16.h>
#include <cstdint>

// Problem constants (fixed by the dataset)
#define D_   64
#define H_   64
#define EF_  16
#define PC   192    // g_P row: [src-proj(+b_e1) | dst-proj | node-proj(+b_n1)]
#define TEE  128    // edges per tile (edge kernel)
#define NMAX 50000

__device__ float g_hneigh[(size_t)NMAX * H_];
__device__ float g_P[(size_t)NMAX * PC];

typedef unsigned int u32;

__device__ __forceinline__ float silu_f(float x) {
    return __fdividef(x, 1.0f + __expf(-x));
}
__device__ __forceinline__ float silu_fast(float x) {
    float t, hx = 0.5f * x;
    asm("tanh.approx.f32 %0, %1;" : "=f"(t) : "f"(hx));
    return fmaf(hx, t, hx);
}
__device__ __forceinline__ u32 smem_u32(const void* p) {
    u32 a;
    asm("{ .reg .u64 t; cvta.to.shared.u64 t, %1; cvt.u32.u64 %0, t; }"
        : "=r"(a) : "l"(p));
    return a;
}

__global__ void zero_hneigh(int n4) {
    float4 z = make_float4(0.f, 0.f, 0.f, 0.f);
    for (int i = blockIdx.x * blockDim.x + threadIdx.x; i < n4;
         i += gridDim.x * blockDim.x)
        reinterpret_cast<float4*>(g_hneigh)[i] = z;
}

extern __shared__ char smemc[];

// ---- mma helpers ----
__device__ __forceinline__ void ldsm_x4(u32& r0, u32& r1, u32& r2, u32& r3, u32 a) {
    asm volatile("ldmatrix.sync.aligned.m8n8.x4.shared.b16 {%0,%1,%2,%3}, [%4];"
                 : "=r"(r0), "=r"(r1), "=r"(r2), "=r"(r3) : "r"(a));
}
__device__ __forceinline__ void ldsm_x2(u32& r0, u32& r1, u32 a) {
    asm volatile("ldmatrix.sync.aligned.m8n8.x2.shared.b16 {%0,%1}, [%2];"
                 : "=r"(r0), "=r"(r1) : "r"(a));
}
__device__ __forceinline__ void mma16816(float* d, const u32* a, const u32* b) {
    asm volatile(
        "mma.sync.aligned.m16n8k16.row.col.f32.bf16.bf16.f32 "
        "{%0,%1,%2,%3}, {%4,%5,%6,%7}, {%8,%9}, {%0,%1,%2,%3};"
        : "+f"(d[0]), "+f"(d[1]), "+f"(d[2]), "+f"(d[3])
        : "r"(a[0]), "r"(a[1]), "r"(a[2]), "r"(a[3]), "r"(b[0]), "r"(b[1]));
}
__device__ __forceinline__ void bf16_split(float x, __nv_bfloat16& h, __nv_bfloat16& l) {
    h = __float2bfloat16(x);
    l = __float2bfloat16(x - __bfloat162float(h));
}

#define MSTRIDE 144        // bytes per row of [*][64] bf16 tiles

// ---------------------------------------------------------------------------
// Precompute, TENSORIZED: g_P[n][0:192] = nf @ Wcat (+ biases)
//   Wcat cols: [We1_src | We1_dst | Wn1_top]; bias: [b_e1 | 0 | b_n1]
// 128-node tiles, split-bf16 3-product HMMA, two 96-col passes.
// ---------------------------------------------------------------------------
#define PO_BIAS 0          // 192 f -> 768
#define PO_WHI  768        // 192 x MSTRIDE -> 28416
#define PO_WLO  28416      // -> 56064
#define PO_ZHI  56064      // 128 x MSTRIDE -> 74496
#define PO_ZLO  74496      // -> 92928
#define PO_TOT  92928

__global__ __launch_bounds__(256, 2) void pre_kernel(
    const float* __restrict__ node_feat,
    const float* __restrict__ W_e1, const float* __restrict__ b_e1,
    const float* __restrict__ W_n1, const float* __restrict__ b_n1, int N)
{
    char* smem = smemc;
    const u32 sb = smem_u32(smem);
    float* biass = (float*)(smem + PO_BIAS);

    const int tid = threadIdx.x;
    const int wid = tid >> 5;
    const int lid = tid & 31;

    // Wcat^T[c][k] split hi/lo (c = output col 0..191, k = 0..63)
    for (int i = tid; i < PC * 64; i += 256) {
        int c = i >> 6, k = i & 63;
        float w;
        if (c < 64)       w = W_e1[k * H_ + c];
        else if (c < 128) w = W_e1[(64 + k) * H_ + (c - 64)];
        else              w = W_n1[k * H_ + (c - 128)];
        __nv_bfloat16 h, l; bf16_split(w, h, l);
        *(__nv_bfloat16*)(smem + PO_WHI + c * MSTRIDE + k * 2) = h;
        *(__nv_bfloat16*)(smem + PO_WLO + c * MSTRIDE + k * 2) = l;
    }
    if (tid < PC) {
        float bv = 0.f;
        if (tid < 64) bv = b_e1[tid];
        else if (tid >= 128) bv = b_n1[tid - 128];
        biass[tid] = bv;
    }

    const int m0  = wid * 16;
    const int rA  = m0 + (lid >> 2);
    const int rB  = rA + 8;
    const int cfr = (lid & 3) * 2;
    const u32 aoff  = (u32)((m0 + (lid & 15)) * MSTRIDE + (lid >> 4) * 16);
    const u32 boffR = (u32)((lid & 7) * MSTRIDE + ((lid >> 3) & 1) * 16);

    const int ntiles = (N + 127) / 128;
    for (int tile = blockIdx.x; tile < ntiles; tile += gridDim.x) {
        const int n0 = tile * 128;
        __syncthreads();   // prior tile's Z reads done (and first-iter W fill)

        // Load node_feat tile -> Zhi/Zlo (16 threads per 64-float row)
        #pragma unroll
        for (int it = 0; it < 8; it++) {
            int idx = it * 256 + tid;
            int r = idx >> 4, k4 = (idx & 15) * 4;
            int n = n0 + r;
            float4 v = (n < N)
                ? *reinterpret_cast<const float4*>(&node_feat[(size_t)n * D_ + k4])
                : make_float4(0.f, 0.f, 0.f, 0.f);
            __nv_bfloat16 h0, h1, h2, h3, l0, l1, l2, l3;
            bf16_split(v.x, h0, l0); bf16_split(v.y, h1, l1);
            bf16_split(v.z, h2, l2); bf16_split(v.w, h3, l3);
            __nv_bfloat162 H01; H01.x = h0; H01.y = h1;
            __nv_bfloat162 H23; H23.x = h2; H23.y = h3;
            __nv_bfloat162 L01; L01.x = l0; L01.y = l1;
            __nv_bfloat162 L23; L23.x = l2; L23.y = l3;
            *(uint2*)(smem + PO_ZHI + r * MSTRIDE + k4 * 2) =
                make_uint2(*(u32*)&H01, *(u32*)&H23);
            *(uint2*)(smem + PO_ZLO + r * MSTRIDE + k4 * 2) =
                make_uint2(*(u32*)&L01, *(u32*)&L23);
        }
        __syncthreads();

        const int nA = n0 + rA, nB = n0 + rB;
        // Two passes of 12 n-tiles (96 cols each) to bound registers
        #pragma unroll
        for (int half = 0; half < 2; half++) {
            float acc[12][4];
            #pragma unroll
            for (int nt = 0; nt < 12; nt++)
                acc[nt][0] = acc[nt][1] = acc[nt][2] = acc[nt][3] = 0.f;
            #pragma unroll
            for (int j = 0; j < 4; j++) {
                u32 ah[4], al[4];
                ldsm_x4(ah[0], ah[1], ah[2], ah[3], sb + PO_ZHI + aoff + j * 32);
                ldsm_x4(al[0], al[1], al[2], al[3], sb + PO_ZLO + aoff + j * 32);
                #pragma unroll
                for (int nt = 0; nt < 12; nt++) {
                    u32 bh[2], bl[2];
                    u32 boff = (u32)((half * 96 + nt * 8) * MSTRIDE) + boffR + j * 32;
                    ldsm_x2(bh[0], bh[1], sb + PO_WHI + boff);
                    ldsm_x2(bl[0], bl[1], sb + PO_WLO + boff);
                    mma16816(acc[nt], ah, bh);
                    mma16816(acc[nt], ah, bl);
                    mma16816(acc[nt], al, bh);
                }
            }
            #pragma unroll
            for (int nt = 0; nt < 12; nt++) {
                int c = half * 96 + nt * 8 + cfr;
                float b0 = biass[c], b1 = biass[c + 1];
                if (nA < N)
                    *reinterpret_cast<float2*>(&g_P[(size_t)nA * PC + c]) =
                        make_float2(acc[nt][0] + b0, acc[nt][1] + b1);
                if (nB < N)
                    *reinterpret_cast<float2*>(&g_P[(size_t)nB * PC + c]) =
                        make_float2(acc[nt][2] + b0, acc[nt][3] + b1);
            }
        }
    }
}

// ---------------------------------------------------------------------------
// Edge kernel — R13 winner, byte-identical (pipelined, staged v4 scatter)
// ---------------------------------------------------------------------------
#define EO_WR   0          // 64 f
#define EO_B2   256        // 64 f
#define EO_WA   512        // 16*64 f -> 4608
#define EO_RAD  4608       // 2 x 128 f -> 5632
#define EO_SRC  5632       // 2 x 128 i -> 6656
#define EO_DST  6656       // 2 x 128 i -> 7680
#define EO_AS   7680       // 2 x 128*17 f -> 25088
#define EO_W2HI 25088      // 64 x MSTRIDE -> 34304
#define EO_W2LO 34304      // -> 43520
#define EO_MHI  43520      // 128 x MSTRIDE -> 61952
#define EO_MLO  61952      // -> 80384
#define EO_MSG  EO_MHI     // alias: msg tile [128][68] f
#define EO_TOT  80384

__global__ __launch_bounds__(256, 2) void edge_kernel(
    const float* __restrict__ coord, const float* __restrict__ edge_feat,
    const int* __restrict__ src, const int* __restrict__ dst,
    const float* __restrict__ W_e1, const float* __restrict__ W_e2,
    const float* __restrict__ b_e2, int E)
{
    char* smem = smemc;
    const u32 sb = smem_u32(smem);
    float* wrs = (float*)(smem + EO_WR);
    float* b2s = (float*)(smem + EO_B2);
    float* Was = (float*)(smem + EO_WA);
    float* Msg = (float*)(smem + EO_MSG);

    const int tid = threadIdx.x;
    const int wid = tid >> 5;
    const int lid = tid & 31;
    const int tx  = tid & 15;
    const int ty  = tid >> 4;

    for (int i = tid; i < EF_ * H_; i += 256) Was[i] = W_e1[129 * H_ + i];
    if (tid < H_) { wrs[tid] = W_e1[128 * H_ + tid]; b2s[tid] = b_e2[tid]; }
    for (int i = tid; i < H_ * H_; i += 256) {
        int k = i >> 6, n = i & 63;
        __nv_bfloat16 hi, lo; bf16_split(W_e2[i], hi, lo);
        *(__nv_bfloat16*)(smem + EO_W2HI + n * MSTRIDE + k * 2) = hi;
        *(__nv_bfloat16*)(smem + EO_W2LO + n * MSTRIDE + k * 2) = lo;
    }

    const int ntiles = (E + TEE - 1) / TEE;
    int tile = blockIdx.x;
    if (tile >= ntiles) return;

#define PHASE_A(tt, bb)                                                        \
    {                                                                          \
        const int e0n = (tt) * TEE;                                            \
        float* radb = (float*)(smem + EO_RAD + (bb) * 512);                    \
        int*   srcb = (int*)(smem + EO_SRC + (bb) * 512);                      \
        int*   dstb = (int*)(smem + EO_DST + (bb) * 512);                      \
        float* Asb  = (float*)(smem + EO_AS + (bb) * 8704);                    \
        if (tid < TEE) {                                                       \
            int e = e0n + tid;                                                 \
            int s = 0, d = 0;                                                  \
            float radial = 0.f;                                                \
            if (e < E) {                                                       \
                s = src[e]; d = dst[e];                                        \
                float dx = coord[3 * s + 0] - coord[3 * d + 0];                \
                float dy = coord[3 * s + 1] - coord[3 * d + 1];                \
                float dz = coord[3 * s + 2] - coord[3 * d + 2];                \
                radial = dx * dx + dy * dy + dz * dz;                          \
            }                                                                  \
            srcb[tid] = s; dstb[tid] = d; radb[tid] = radial;                  \
        }                                                                      \
        _Pragma("unroll")                                                      \
        for (int it = 0; it < 8; it++) {                                       \
            int idx = it * 256 + tid;                                          \
            int r = idx >> 4, j = idx & 15;                                    \
            int e = e0n + r;                                                   \
            Asb[r * 17 + j] = (e < E) ? edge_feat[(size_t)e * EF_ + j] : 0.f;  \
        }                                                                      \
    }

#define GATHER(bb, ps)                                                         \
    {                                                                          \
        int* srcb = (int*)(smem + EO_SRC + (bb) * 512);                        \
        int* dstb = (int*)(smem + EO_DST + (bb) * 512);                        \
        _Pragma("unroll")                                                      \
        for (int i = 0; i < 8; i++) {                                          \
            int r = ty * 8 + i;                                                \
            float4 a = *reinterpret_cast<const float4*>(                       \
                           &g_P[(size_t)srcb[r] * PC + tx * 4]);               \
            float4 bq = *reinterpret_cast<const float4*>(                      \
                           &g_P[(size_t)dstb[r] * PC + 64 + tx * 4]);          \
            ps[i] = make_float4(a.x + bq.x, a.y + bq.y, a.z + bq.z, a.w + bq.w);\
        }                                                                      \
    }

    int b = 0;
    float4 psum[8];
    PHASE_A(tile, 0);
    __syncthreads();
    GATHER(0, psum);

    for (; tile < ntiles; tile += gridDim.x) {
        const int e0 = tile * TEE;
        const int tnext = tile + gridDim.x;
        float* radb = (float*)(smem + EO_RAD + b * 512);
        int*   dstb = (int*)(smem + EO_DST + b * 512);
        float* Asb  = (float*)(smem + EO_AS + b * 8704);

        // Stage 1
        const float4 wr = *reinterpret_cast<const float4*>(&wrs[tx * 4]);
        #pragma unroll
        for (int g = 0; g < 2; g++) {
            const int rbase = ty * 8 + g * 4;
            float acc[4][4];
            #pragma unroll
            for (int i = 0; i < 4; i++) {
                float rr = radb[rbase + i];
                acc[i][0] = rr * wr.x; acc[i][1] = rr * wr.y;
                acc[i][2] = rr * wr.z; acc[i][3] = rr * wr.w;
            }
            #pragma unroll
            for (int k = 0; k < EF_; k++) {
                const float4 w = *reinterpret_cast<const float4*>(&Was[k * H_ + tx * 4]);
                #pragma unroll
                for (int i = 0; i < 4; i++) {
                    float a = Asb[(rbase + i) * 17 + k];
                    acc[i][0] += a * w.x; acc[i][1] += a * w.y;
                    acc[i][2] += a * w.z; acc[i][3] += a * w.w;
                }
            }
            #pragma unroll
            for (int i = 0; i < 4; i++) {
                int r = rbase + i;
                const float4 p = psum[g * 4 + i];
                float m0 = silu_fast(acc[i][0] + p.x);
                float m1 = silu_fast(acc[i][1] + p.y);
                float m2 = silu_fast(acc[i][2] + p.z);
                float m3 = silu_fast(acc[i][3] + p.w);
                __nv_bfloat16 h0, h1, h2, h3, l0, l1, l2, l3;
                bf16_split(m0, h0, l0); bf16_split(m1, h1, l1);
                bf16_split(m2, h2, l2); bf16_split(m3, h3, l3);
                __nv_bfloat162 H01; H01.x = h0; H01.y = h1;
                __nv_bfloat162 H23; H23.x = h2; H23.y = h3;
                __nv_bfloat162 L01; L01.x = l0; L01.y = l1;
                __nv_bfloat162 L23; L23.x = l2; L23.y = l3;
                *(uint2*)(smem + EO_MHI + r * MSTRIDE + tx * 8) =
                    make_uint2(*(u32*)&H01, *(u32*)&H23);
                *(uint2*)(smem + EO_MLO + r * MSTRIDE + tx * 8) =
                    make_uint2(*(u32*)&L01, *(u32*)&L23);
            }
        }

        if (tnext < ntiles) PHASE_A(tnext, b ^ 1);
        __syncthreads();

        // Stage 2
        float acc[8][4];
        {
            const int m0 = wid * 16;
            #pragma unroll
            for (int nt = 0; nt < 8; nt++)
                acc[nt][0] = acc[nt][1] = acc[nt][2] = acc[nt][3] = 0.f;

            const u32 aoff = (u32)((m0 + (lid & 15)) * MSTRIDE + (lid >> 4) * 16);
            const u32 boffR = (u32)((lid & 7) * MSTRIDE + ((lid >> 3) & 1) * 16);
            #pragma unroll
            for (int j = 0; j < 4; j++) {
                u32 ah[4], al[4];
                ldsm_x4(ah[0], ah[1], ah[2], ah[3], sb + EO_MHI + aoff + j * 32);
                ldsm_x4(al[0], al[1], al[2], al[3], sb + EO_MLO + aoff + j * 32);
                #pragma unroll
                for (int nt = 0; nt < 8; nt++) {
                    u32 bh[2], bl[2];
                    u32 boff = (u32)(nt * 8 * MSTRIDE) + boffR + j * 32;
                    ldsm_x2(bh[0], bh[1], sb + EO_W2HI + boff);
                    ldsm_x2(bl[0], bl[1], sb + EO_W2LO + boff);
                    mma16816(acc[nt], ah, bh);
                    mma16816(acc[nt], ah, bl);
                    mma16816(acc[nt], al, bh);
                }
            }
        }
        __syncthreads();

        if (tnext < ntiles) GATHER(b ^ 1, psum);

        // Epilogue A: bias + silu -> Msg tile
        {
            const int rA = wid * 16 + (lid >> 2);
            const int rB = rA + 8;
            const int c0base = (lid & 3) * 2;
            #pragma unroll
            for (int nt = 0; nt < 8; nt++) {
                const int c = nt * 8 + c0base;
                const float bb0 = b2s[c], bb1 = b2s[c + 1];
                float2 vA = make_float2(silu_fast(acc[nt][0] + bb0),
                                        silu_fast(acc[nt][1] + bb1));
                float2 vB = make_float2(silu_fast(acc[nt][2] + bb0),
                                        silu_fast(acc[nt][3] + bb1));
                *reinterpret_cast<float2*>(&Msg[rA * 68 + c]) = vA;
                *reinterpret_cast<float2*>(&Msg[rB * 68 + c]) = vB;
            }
        }
        __syncthreads();

        // Epilogue B: row-coalesced v4 scatter
        {
            const int nvalid = min(TEE, E - e0);
            #pragma unroll
            for (int it = 0; it < 8; it++) {
                int slot = it * 256 + tid;
                int r = slot >> 4, ch = slot & 15;
                if (r < nvalid) {
                    float4 v = *reinterpret_cast<const float4*>(&Msg[r * 68 + ch * 4]);
                    float* p = &g_hneigh[(size_t)dstb[r] * H_ + ch * 4];
                    asm volatile("red.global.add.v4.f32 [%0], {%1,%2,%3,%4};"
                                 :: "l"(p), "f"(v.x), "f"(v.y), "f"(v.z), "f"(v.w)
                                 : "memory");
                }
            }
        }
        __syncthreads();
        b ^= 1;
    }
#undef PHASE_A
#undef GATHER
}

// ---------------------------------------------------------------------------
// Node kernel, tensorized (R8 winner, unchanged)
// ---------------------------------------------------------------------------
#define NO_W1HI 0
#define NO_W1LO 9216
#define NO_W2HI 18432
#define NO_W2LO 27648
#define NO_B2   36864
#define NO_ZHI  37120
#define NO_ZLO  55552
#define NO_TOT  73984

__global__ __launch_bounds__(256, 2) void node_kernel(
    const float* __restrict__ W_n1, const float* __restrict__ W_n2,
    const float* __restrict__ b_n2, float* __restrict__ out, int N)
{
    char* smem = smemc;
    const u32 sb = smem_u32(smem);
    float* b2s = (float*)(smem + NO_B2);

    const int tid = threadIdx.x;
    const int wid = tid >> 5;
    const int lid = tid & 31;

    for (int i = tid; i < 64 * 64; i += 256) {
        int c = i >> 6, k = i & 63;
        __nv_bfloat16 h, l;
        bf16_split(W_n1[(64 + k) * 64 + c], h, l);
        *(__nv_bfloat16*)(smem + NO_W1HI + c * MSTRIDE + k * 2) = h;
        *(__nv_bfloat16*)(smem + NO_W1LO + c * MSTRIDE + k * 2) = l;
        bf16_split(W_n2[k * 64 + c], h, l);
        *(__nv_bfloat16*)(smem + NO_W2HI + c * MSTRIDE + k * 2) = h;
        *(__nv_bfloat16*)(smem + NO_W2LO + c * MSTRIDE + k * 2) = l;
    }
    if (tid < 64) b2s[tid] = b_n2[tid];

    const int m0  = wid * 16;
    const int rA  = m0 + (lid >> 2);
    const int rB  = rA + 8;
    const int cfr = (lid & 3) * 2;
    const u32 aoff  = (u32)((m0 + (lid & 15)) * MSTRIDE + (lid >> 4) * 16);
    const u32 boffR = (u32)((lid & 7) * MSTRIDE + ((lid >> 3) & 1) * 16);

    const int ntiles = (N + 127) / 128;
    for (int tile = blockIdx.x; tile < ntiles; tile += gridDim.x) {
        const int n0 = tile * 128;
        __syncthreads();

        #pragma unroll
        for (int it = 0; it < 8; it++) {
            int idx = it * 256 + tid;
            int r = idx >> 4, k4 = (idx & 15) * 4;
            int n = n0 + r;
            float4 v = (n < N)
                ? *reinterpret_cast<const float4*>(&g_hneigh[(size_t)n * H_ + k4])
                : make_float4(0.f, 0.f, 0.f, 0.f);
            __nv_bfloat16 h0, h1, h2, h3, l0, l1, l2, l3;
            bf16_split(v.x, h0, l0); bf16_split(v.y, h1, l1);
            bf16_split(v.z, h2, l2); bf16_split(v.w, h3, l3);
            __nv_bfloat162 H01; H01.x = h0; H01.y = h1;
            __nv_bfloat162 H23; H23.x = h2; H23.y = h3;
            __nv_bfloat162 L01; L01.x = l0; L01.y = l1;
            __nv_bfloat162 L23; L23.x = l2; L23.y = l3;
            *(uint2*)(smem + NO_ZHI + r * MSTRIDE + k4 * 2) =
                make_uint2(*(u32*)&H01, *(u32*)&H23);
            *(uint2*)(smem + NO_ZLO + r * MSTRIDE + k4 * 2) =
                make_uint2(*(u32*)&L01, *(u32*)&L23);
        }
        __syncthreads();

        float acc[8][4];
        {
            const int nA = n0 + rA, nB = n0 + rB;
            #pragma unroll
            for (int nt = 0; nt < 8; nt++) {
                int c = nt * 8 + cfr;
                float2 pA = (nA < N)
                    ? *reinterpret_cast<const float2*>(&g_P[(size_t)nA * PC + 128 + c])
                    : make_float2(0.f, 0.f);
                float2 pB = (nB < N)
                    ? *reinterpret_cast<const float2*>(&g_P[(size_t)nB * PC + 128 + c])
                    : make_float2(0.f, 0.f);
                acc[nt][0] = pA.x; acc[nt][1] = pA.y;
                acc[nt][2] = pB.x; acc[nt][3] = pB.y;
            }
            #pragma unroll
            for (int j = 0; j < 4; j++) {
                u32 ah[4], al[4];
                ldsm_x4(ah[0], ah[1], ah[2], ah[3], sb + NO_ZHI + aoff + j * 32);
                ldsm_x4(al[0], al[1], al[2], al[3], sb + NO_ZLO + aoff + j * 32);
                #pragma unroll
                for (int nt = 0; nt < 8; nt++) {
                    u32 bh[2], bl[2];
                    u32 boff = (u32)(nt * 8 * MSTRIDE) + boffR + j * 32;
                    ldsm_x2(bh[0], bh[1], sb + NO_W1HI + boff);
                    ldsm_x2(bl[0], bl[1], sb + NO_W1LO + boff);
                    mma16816(acc[nt], ah, bh);
                    mma16816(acc[nt], ah, bl);
                    mma16816(acc[nt], al, bh);
                }
            }
        }
        __syncthreads();

        #pragma unroll
        for (int nt = 0; nt < 8; nt++) {
            int c = nt * 8 + cfr;
            float v0 = silu_f(acc[nt][0]);
            float v1 = silu_f(acc[nt][1]);
            float v2 = silu_f(acc[nt][2]);
            float v3 = silu_f(acc[nt][3]);
            __nv_bfloat16 h0, h1, h2, h3, l0, l1, l2, l3;
            bf16_split(v0, h0, l0); bf16_split(v1, h1, l1);
            bf16_split(v2, h2, l2); bf16_split(v3, h3, l3);
            __nv_bfloat162 HA; HA.x = h0; HA.y = h1;
            __nv_bfloat162 HB; HB.x = h2; HB.y = h3;
            __nv_bfloat162 LA; LA.x = l0; LA.y = l1;
            __nv_bfloat162 LB; LB.x = l2; LB.y = l3;
            *(u32*)(smem + NO_ZHI + rA * MSTRIDE + c * 2) = *(u32*)&HA;
            *(u32*)(smem + NO_ZHI + rB * MSTRIDE + c * 2) = *(u32*)&HB;
            *(u32*)(smem + NO_ZLO + rA * MSTRIDE + c * 2) = *(u32*)&LA;
            *(u32*)(smem + NO_ZLO + rB * MSTRIDE + c * 2) = *(u32*)&LB;
        }
        __syncthreads();

        float acc2[8][4];
        {
            #pragma unroll
            for (int nt = 0; nt < 8; nt++) {
                int c = nt * 8 + cfr;
                float b0 = b2s[c], b1 = b2s[c + 1];
                acc2[nt][0] = b0; acc2[nt][1] = b1;
                acc2[nt][2] = b0; acc2[nt][3] = b1;
            }
            #pragma unroll
            for (int j = 0; j < 4; j++) {
                u32 ah[4], al[4];
                ldsm_x4(ah[0], ah[1], ah[2], ah[3], sb + NO_ZHI + aoff + j * 32);
                ldsm_x4(al[0], al[1], al[2], al[3], sb + NO_ZLO + aoff + j * 32);
                #pragma unroll
                for (int nt = 0; nt < 8; nt++) {
                    u32 bh[2], bl[2];
                    u32 boff = (u32)(nt * 8 * MSTRIDE) + boffR + j * 32;
                    ldsm_x2(bh[0], bh[1], sb + NO_W2HI + boff);
                    ldsm_x2(bl[0], bl[1], sb + NO_W2LO + boff);
                    mma16816(acc2[nt], ah, bh);
                    mma16816(acc2[nt], ah, bl);
                    mma16816(acc2[nt], al, bh);
                }
            }
        }

        {
            const int nA = n0 + rA, nB = n0 + rB;
            #pragma unroll
            for (int nt = 0; nt < 8; nt++) {
                int c = nt * 8 + cfr;
                if (nA < N)
                    *reinterpret_cast<float2*>(&out[(size_t)nA * D_ + c]) =
                        make_float2(acc2[nt][0], acc2[nt][1]);
                if (nB < N)
                    *reinterpret_cast<float2*>(&out[(size_t)nB * D_ + c]) =
                        make_float2(acc2[nt][2], acc2[nt][3]);
            }
        }
    }
}

extern "C" void kernel_launch(void* const* d_in, const int* in_sizes, int n_in,
                              void* d_out, int out_size)
{
    const float* node_feat = (const float*)d_in[0];
    const float* coord     = (const float*)d_in[1];
    const float* edge_feat = (const float*)d_in[2];
    const int*   src       = (const int*)d_in[3];
    const int*   dst       = (const int*)d_in[4];
    const float* W_e1      = (const float*)d_in[5];
    const float* b_e1      = (const float*)d_in[6];
    const float* W_e2      = (const float*)d_in[7];
    const float* b_e2      = (const float*)d_in[8];
    const float* W_n1      = (const float*)d_in[9];
    const float* b_n1      = (const float*)d_in[10];
    const float* W_n2      = (const float*)d_in[11];
    const float* b_n2      = (const float*)d_in[12];
    float* out = (float*)d_out;

    const int N = in_sizes[0] / D_;
    const int E = in_sizes[3];

    cudaFuncSetAttribute(pre_kernel,
                         cudaFuncAttributeMaxDynamicSharedMemorySize, PO_TOT);
    cudaFuncSetAttribute(edge_kernel,
                         cudaFuncAttributeMaxDynamicSharedMemorySize, EO_TOT);
    cudaFuncSetAttribute(node_kernel,
                         cudaFuncAttributeMaxDynamicSharedMemorySize, NO_TOT);

    zero_hneigh<<<512, 256>>>(N * H_ / 4);
    pre_kernel<<<296, 256, PO_TOT>>>(node_feat, W_e1, b_e1, W_n1, b_n1, N);
    edge_kernel<<<296, 256, EO_TOT>>>(coord, edge_feat, src, dst,
                                      W_e1, W_e2, b_e2, E);
    node_kernel<<<296, 256, NO_TOT>>>(W_n1, W_n2, b_n2, out, N);
}